// round 11
// baseline (speedup 1.0000x reference)
#include <cuda_runtime.h>
#include <math.h>

#define BB 64
#define CC 100
#define TT 2000
#define KK 200
#define DD 2048
#define NTILE 10
#define NCHUNK 5                 // K split for feat
#define KCH (KK / NCHUNK)        // 40

#define GROUP_SIZE   31                           // 10 sup + 20 feat + 1 bce per row
#define TOTAL_BLOCKS (BB * GROUP_SIZE)            // 1984
#define ROW_ARRIVALS GROUP_SIZE                   // 31 per row

// Deterministic partial buffers — plain writes, no zeroing needed.
__device__ float  g_sup_sq_p[BB * NTILE * CC];        // [b][tile][c]
__device__ float  g_sup_cnt_p[BB * NTILE * CC];       // [b][tile][c]
__device__ float4 g_feat_vec[2 * BB * NCHUNK * 512];  // [which][b][chunk][d4]
__device__ float  g_bce[BB * 2];                      // [b][{cls,be}]
__device__ float  g_row[BB * 3];                      // [b][{sup, vcnt, um}]
// Arrival counters — reset by the final block each run (graph-replay safe).
__device__ unsigned int g_row_done[BB];
__device__ unsigned int g_fin_done;

__global__ void __launch_bounds__(256) mega_kernel(
        const float4* __restrict__ fa, const float4* __restrict__ fb,
        const float4* __restrict__ gt, const float4* __restrict__ cas,
        const float* __restrict__ score_act,
        const float* __restrict__ score_bkg,
        const float* __restrict__ label,
        float* __restrict__ out) {
    const int tid = threadIdx.x;       // 0..255
    const int tx  = tid & 31;
    const int ty  = tid >> 5;          // 0..7
    const int lane = tx, wrp = ty;

    // Interleaved mapping: all 31 contributors of row b are adjacent in launch
    // order, so every wave carries the full sup/feat/bce traffic mix and row
    // reducers fire early.
    const int my_b = blockIdx.x / GROUP_SIZE;   // 0..63
    const int role = blockIdx.x % GROUP_SIZE;   // 0..30

    if (role < NTILE) {
        // ---- sup tile: (b, tile) over 200 time steps ----
        const int tile = role;
        const int tb   = tile * 200;

        float4 sq  = make_float4(0.f, 0.f, 0.f, 0.f);
        float4 cnt = make_float4(0.f, 0.f, 0.f, 0.f);

        if (tx < CC / 4) {
            const size_t base = (size_t)my_b * TT * (CC / 4) + (size_t)tb * (CC / 4) + tx;
#pragma unroll 5
            for (int j = 0; j < 25; j++) {
                const size_t idx = base + (size_t)(ty + 8 * j) * (CC / 4);
                float4 g = gt[idx];
                float4 c = cas[idx];
                float pm, d;
                pm = (g.x > 0.5f) ? 1.f : 0.f; d = c.x - pm; sq.x += d * d; cnt.x += pm;
                pm = (g.y > 0.5f) ? 1.f : 0.f; d = c.y - pm; sq.y += d * d; cnt.y += pm;
                pm = (g.z > 0.5f) ? 1.f : 0.f; d = c.z - pm; sq.z += d * d; cnt.z += pm;
                pm = (g.w > 0.5f) ? 1.f : 0.f; d = c.w - pm; sq.w += d * d; cnt.w += pm;
            }
        }

        __shared__ float s_sq[CC], s_cnt[CC];
        if (tid < CC) { s_sq[tid] = 0.f; s_cnt[tid] = 0.f; }
        __syncthreads();
        if (tx < CC / 4) {
            atomicAdd(&s_sq[tx * 4 + 0], sq.x);  atomicAdd(&s_cnt[tx * 4 + 0], cnt.x);
            atomicAdd(&s_sq[tx * 4 + 1], sq.y);  atomicAdd(&s_cnt[tx * 4 + 1], cnt.y);
            atomicAdd(&s_sq[tx * 4 + 2], sq.z);  atomicAdd(&s_cnt[tx * 4 + 2], cnt.z);
            atomicAdd(&s_sq[tx * 4 + 3], sq.w);  atomicAdd(&s_cnt[tx * 4 + 3], cnt.w);
        }
        __syncthreads();
        if (tid < CC) {
            const int o = my_b * (NTILE * CC) + tile * CC + tid;
            g_sup_sq_p[o]  = s_sq[tid];
            g_sup_cnt_p[o] = s_cnt[tid];
        }
    } else if (role < NTILE + 2 * 2 * NCHUNK) {
        // ---- feat chunk: (which, dpart, chunk) for row my_b — 40 k-steps ----
        const int idx   = role - NTILE;             // 0..19
        const int which = idx / (2 * NCHUNK);       // 0..1
        const int rem   = idx % (2 * NCHUNK);
        const int dpart = rem / NCHUNK;             // 0..1
        const int chunk = rem % NCHUNK;             // 0..4
        const float4* __restrict__ f = which ? fb : fa;

        const int d4 = dpart * 256 + tid;           // 0..511
        const float4* p = f + (size_t)my_b * KK * (DD / 4)
                            + (size_t)(chunk * KCH) * (DD / 4) + d4;

        float4 s = make_float4(0.f, 0.f, 0.f, 0.f);
#pragma unroll 8
        for (int k = 0; k < KCH; k++) {
            float4 v = p[(size_t)k * (DD / 4)];
            s.x += v.x; s.y += v.y; s.z += v.z; s.w += v.w;
        }
        g_feat_vec[((which * BB + my_b) * NCHUNK + chunk) * 512 + d4] = s;
    } else {
        // ---- BCE partials for row my_b (all 256 threads hit barriers) ----
        __shared__ float r[128];
        __shared__ float s_rowsum;
        const int i = my_b * CC + ((tid < CC) ? tid : 0);
        const float lab = (tid < CC) ? label[i] : 0.f;

        if (tid < 128) r[tid] = lab;
        __syncthreads();
#pragma unroll
        for (int o = 64; o > 0; o >>= 1) {
            if (tid < o) r[tid] += r[tid + o];
            __syncthreads();
        }
        if (tid == 0) s_rowsum = r[0];
        __syncthreads();
        const float rowsum = s_rowsum;

        float cls = 0.f, be = 0.f;
        const float invC = 1.0f / (float)CC;
        if (tid < CC) {
            const float y = lab / rowsum;
            const float p = score_act[i];
            cls = -(y * fmaxf(logf(p), -100.f) + (1.f - y) * fmaxf(logf(1.f - p), -100.f));
            const float pb = score_bkg[i];
            be = -(invC * fmaxf(logf(pb), -100.f) + (1.f - invC) * fmaxf(logf(1.f - pb), -100.f));
        }
        if (tid < 128) r[tid] = cls;
        __syncthreads();
#pragma unroll
        for (int o = 64; o > 0; o >>= 1) {
            if (tid < o) r[tid] += r[tid + o];
            __syncthreads();
        }
        if (tid == 0) g_bce[my_b * 2 + 0] = r[0];
        __syncthreads();
        if (tid < 128) r[tid] = be;
        __syncthreads();
#pragma unroll
        for (int o = 64; o > 0; o >>= 1) {
            if (tid < o) r[tid] += r[tid + o];
            __syncthreads();
        }
        if (tid == 0) g_bce[my_b * 2 + 1] = r[0];
    }

    // ---- level 1: row arrival; the 31st block reduces row my_b ----
    __syncthreads();
    __shared__ bool s_do_row;
    if (tid == 0) {
        __threadfence();
        s_do_row = (atomicAdd(&g_row_done[my_b], 1u) == ROW_ARRIVALS - 1);
    }
    __syncthreads();
    if (!s_do_row) return;

    {
        // sup per-class combine (tid < 100)
        float sup = 0.f, vcnt = 0.f;
        if (tid < CC) {
            float sq = 0.f, cnt = 0.f;
            const int base = my_b * (NTILE * CC) + tid;
#pragma unroll
            for (int t = 0; t < NTILE; t++) {
                sq  += g_sup_sq_p[base + t * CC];
                cnt += g_sup_cnt_p[base + t * CC];
            }
            if (cnt > 0.f) { sup = sqrtf(sq); vcnt = 1.f; }
        }

        // feat norm²: combine 5 chunk vectors per d, square (L2-hot, 80 KB)
        float na2 = 0.f, nb2 = 0.f;
#pragma unroll
        for (int which = 0; which < 2; which++) {
            const float4* base = &g_feat_vec[((which * BB + my_b) * NCHUNK) * 512];
#pragma unroll
            for (int rep = 0; rep < 2; rep++) {
                const int d4 = rep * 256 + tid;
                float4 s = make_float4(0.f, 0.f, 0.f, 0.f);
#pragma unroll
                for (int c = 0; c < NCHUNK; c++) {
                    float4 v = base[c * 512 + d4];
                    s.x += v.x; s.y += v.y; s.z += v.z; s.w += v.w;
                }
                const float d2 = s.x * s.x + s.y * s.y + s.z * s.z + s.w * s.w;
                if (which == 0) na2 += d2; else nb2 += d2;
            }
        }

#pragma unroll
        for (int o = 16; o > 0; o >>= 1) {
            sup  += __shfl_down_sync(0xffffffff, sup,  o);
            vcnt += __shfl_down_sync(0xffffffff, vcnt, o);
            na2  += __shfl_down_sync(0xffffffff, na2,  o);
            nb2  += __shfl_down_sync(0xffffffff, nb2,  o);
        }
        __shared__ float s_r[8][4];
        if (lane == 0) { s_r[wrp][0] = sup; s_r[wrp][1] = vcnt; s_r[wrp][2] = na2; s_r[wrp][3] = nb2; }
        __syncthreads();
        if (tid == 0) {
            float st = 0.f, vt = 0.f, a2 = 0.f, b2 = 0.f;
#pragma unroll
            for (int w = 0; w < 8; w++) {
                st += s_r[w][0]; vt += s_r[w][1]; a2 += s_r[w][2]; b2 += s_r[w][3];
            }
            const float na = sqrtf(a2) / (float)KK;   // ||mean feat_act||
            const float nb = sqrtf(b2) / (float)KK;   // ||mean feat_bkg||
            const float la = fmaxf(100.f - na, 0.f);
            const float t  = la + nb;
            g_row[my_b * 3 + 0] = st;
            g_row[my_b * 3 + 1] = vt;
            g_row[my_b * 3 + 2] = t * t;
        }
    }

    // ---- level 2: final arrival; the 64th row-reducer combines ----
    __syncthreads();
    __shared__ bool s_do_fin;
    if (tid == 0) {
        __threadfence();
        s_do_fin = (atomicAdd(&g_fin_done, 1u) == BB - 1);
    }
    __syncthreads();
    if (!s_do_fin) return;

    {
        float cls = 0.f, be = 0.f, st = 0.f, vt = 0.f, um = 0.f;
        if (tid < BB) {
            cls = g_bce[tid * 2 + 0];
            be  = g_bce[tid * 2 + 1];
            st  = g_row[tid * 3 + 0];
            vt  = g_row[tid * 3 + 1];
            um  = g_row[tid * 3 + 2];
        }
#pragma unroll
        for (int o = 16; o > 0; o >>= 1) {
            cls += __shfl_down_sync(0xffffffff, cls, o);
            be  += __shfl_down_sync(0xffffffff, be,  o);
            st  += __shfl_down_sync(0xffffffff, st,  o);
            vt  += __shfl_down_sync(0xffffffff, vt,  o);
            um  += __shfl_down_sync(0xffffffff, um,  o);
        }
        __shared__ float sw[2][5];
        if (lane == 0 && wrp < 2) {
            sw[wrp][0] = cls; sw[wrp][1] = be; sw[wrp][2] = st; sw[wrp][3] = vt; sw[wrp][4] = um;
        }
        __syncthreads();
        if (tid == 0) {
            const float loss = (sw[0][0] + sw[1][0]) / (float)(BB * CC)
                             + 0.0005f * ((sw[0][4] + sw[1][4]) / (float)BB)
                             + 0.2f * ((sw[0][1] + sw[1][1]) / (float)(BB * CC))
                             + 1.0f * ((sw[0][2] + sw[1][2]) / (sw[0][3] + sw[1][3]));
            out[0] = loss;
            g_fin_done = 0;                 // reset for next replay
        }
        if (tid < BB) g_row_done[tid] = 0;  // reset for next replay
    }
}

extern "C" void kernel_launch(void* const* d_in, const int* in_sizes, int n_in,
                              void* d_out, int out_size) {
    const float*  score_act = (const float*)d_in[0];
    const float*  score_bkg = (const float*)d_in[1];
    const float4* feat_act  = (const float4*)d_in[2];
    const float4* feat_bkg  = (const float4*)d_in[3];
    const float*  label     = (const float*)d_in[4];
    const float4* gt        = (const float4*)d_in[5];
    const float4* cas       = (const float4*)d_in[6];

    mega_kernel<<<TOTAL_BLOCKS, 256>>>(feat_act, feat_bkg, gt, cas,
                                       score_act, score_bkg, label,
                                       (float*)d_out);
}

// round 12
// speedup vs baseline: 1.0705x; 1.0705x over previous
#include <cuda_runtime.h>
#include <math.h>

#define BB 64
#define CC 100
#define TT 2000
#define KK 200
#define DD 2048
#define NTILE 10
#define NCHUNK 5                 // K split for feat
#define KCH (KK / NCHUNK)        // 40

#define SUP_BLOCKS   (BB * NTILE)                 // 640
#define FEAT_BLOCKS  (2 * BB * 2 * NCHUNK)        // 1280
#define BCE_BLOCKS   (BB)                         // 64
#define TOTAL_BLOCKS (SUP_BLOCKS + FEAT_BLOCKS + BCE_BLOCKS)  // 1984
#define ROW_ARRIVALS (NTILE + 2 * 2 * NCHUNK + 1) // 31 per row

// Deterministic partial buffers — plain writes, no zeroing needed.
__device__ float  g_sup_sq_p[BB * NTILE * CC];        // [b][tile][c]
__device__ float  g_sup_cnt_p[BB * NTILE * CC];       // [b][tile][c]
__device__ float4 g_feat_vec[2 * BB * NCHUNK * 512];  // [which][b][chunk][d4]
__device__ float  g_bce[BB * 2];                      // [b][{cls,be}]
__device__ float  g_row[BB * 3];                      // [b][{sup, vcnt, um}]
// Arrival counters — reset by the final block each run (graph-replay safe).
__device__ unsigned int g_row_done[BB];
__device__ unsigned int g_fin_done;

__global__ void __launch_bounds__(256) mega_kernel(
        const float4* __restrict__ fa, const float4* __restrict__ fb,
        const float4* __restrict__ gt, const float4* __restrict__ cas,
        const float* __restrict__ score_act,
        const float* __restrict__ score_bkg,
        const float* __restrict__ label,
        float* __restrict__ out) {
    const int blk = blockIdx.x;
    const int tid = threadIdx.x;       // 0..255
    const int tx  = tid & 31;
    const int ty  = tid >> 5;          // 0..7
    const int lane = tx, wrp = ty;

    int my_b;  // the batch row this block contributes to

    if (blk < SUP_BLOCKS) {
        // ---- sup tile: (b, tile) over 200 time steps ----
        const int b    = blk / NTILE;
        const int tile = blk % NTILE;
        const int tb   = tile * 200;
        my_b = b;

        float4 sq  = make_float4(0.f, 0.f, 0.f, 0.f);
        float4 cnt = make_float4(0.f, 0.f, 0.f, 0.f);

        if (tx < CC / 4) {
            const size_t base = (size_t)b * TT * (CC / 4) + (size_t)tb * (CC / 4) + tx;
#pragma unroll 5
            for (int j = 0; j < 25; j++) {
                const size_t idx = base + (size_t)(ty + 8 * j) * (CC / 4);
                float4 g = gt[idx];
                float4 c = cas[idx];
                float pm, d;
                pm = (g.x > 0.5f) ? 1.f : 0.f; d = c.x - pm; sq.x += d * d; cnt.x += pm;
                pm = (g.y > 0.5f) ? 1.f : 0.f; d = c.y - pm; sq.y += d * d; cnt.y += pm;
                pm = (g.z > 0.5f) ? 1.f : 0.f; d = c.z - pm; sq.z += d * d; cnt.z += pm;
                pm = (g.w > 0.5f) ? 1.f : 0.f; d = c.w - pm; sq.w += d * d; cnt.w += pm;
            }
        }

        __shared__ float s_sq[CC], s_cnt[CC];
        if (tid < CC) { s_sq[tid] = 0.f; s_cnt[tid] = 0.f; }
        __syncthreads();
        if (tx < CC / 4) {
            atomicAdd(&s_sq[tx * 4 + 0], sq.x);  atomicAdd(&s_cnt[tx * 4 + 0], cnt.x);
            atomicAdd(&s_sq[tx * 4 + 1], sq.y);  atomicAdd(&s_cnt[tx * 4 + 1], cnt.y);
            atomicAdd(&s_sq[tx * 4 + 2], sq.z);  atomicAdd(&s_cnt[tx * 4 + 2], cnt.z);
            atomicAdd(&s_sq[tx * 4 + 3], sq.w);  atomicAdd(&s_cnt[tx * 4 + 3], cnt.w);
        }
        __syncthreads();
        if (tid < CC) {
            const int o = b * (NTILE * CC) + tile * CC + tid;
            g_sup_sq_p[o]  = s_sq[tid];
            g_sup_cnt_p[o] = s_cnt[tid];
        }
    } else if (blk < SUP_BLOCKS + FEAT_BLOCKS) {
        // ---- feat chunk: (which, b, dpart, chunk) — 40 k-steps, vector partial ----
        const int idx   = blk - SUP_BLOCKS;         // 0..1279
        const int which = idx / (BB * 2 * NCHUNK);  // 0..1
        int rem = idx % (BB * 2 * NCHUNK);
        const int b     = rem / (2 * NCHUNK);       // 0..63
        rem %= (2 * NCHUNK);
        const int dpart = rem / NCHUNK;             // 0..1
        const int chunk = rem % NCHUNK;             // 0..4
        my_b = b;
        const float4* __restrict__ f = which ? fb : fa;

        const int d4 = dpart * 256 + tid;           // 0..511
        const float4* p = f + (size_t)b * KK * (DD / 4)
                            + (size_t)(chunk * KCH) * (DD / 4) + d4;

        float4 s = make_float4(0.f, 0.f, 0.f, 0.f);
#pragma unroll 8
        for (int k = 0; k < KCH; k++) {
            float4 v = p[(size_t)k * (DD / 4)];
            s.x += v.x; s.y += v.y; s.z += v.z; s.w += v.w;
        }
        g_feat_vec[((which * BB + b) * NCHUNK + chunk) * 512 + d4] = s;
    } else {
        // ---- BCE partials for row b (all 256 threads hit barriers) ----
        const int b = blk - SUP_BLOCKS - FEAT_BLOCKS;
        my_b = b;
        __shared__ float r[128];
        __shared__ float s_rowsum;
        const int i = b * CC + ((tid < CC) ? tid : 0);
        const float lab = (tid < CC) ? label[i] : 0.f;

        if (tid < 128) r[tid] = lab;
        __syncthreads();
#pragma unroll
        for (int o = 64; o > 0; o >>= 1) {
            if (tid < o) r[tid] += r[tid + o];
            __syncthreads();
        }
        if (tid == 0) s_rowsum = r[0];
        __syncthreads();
        const float rowsum = s_rowsum;

        float cls = 0.f, be = 0.f;
        const float invC = 1.0f / (float)CC;
        if (tid < CC) {
            const float y = lab / rowsum;
            const float p = score_act[i];
            cls = -(y * fmaxf(logf(p), -100.f) + (1.f - y) * fmaxf(logf(1.f - p), -100.f));
            const float pb = score_bkg[i];
            be = -(invC * fmaxf(logf(pb), -100.f) + (1.f - invC) * fmaxf(logf(1.f - pb), -100.f));
        }
        if (tid < 128) r[tid] = cls;
        __syncthreads();
#pragma unroll
        for (int o = 64; o > 0; o >>= 1) {
            if (tid < o) r[tid] += r[tid + o];
            __syncthreads();
        }
        if (tid == 0) g_bce[b * 2 + 0] = r[0];
        __syncthreads();
        if (tid < 128) r[tid] = be;
        __syncthreads();
#pragma unroll
        for (int o = 64; o > 0; o >>= 1) {
            if (tid < o) r[tid] += r[tid + o];
            __syncthreads();
        }
        if (tid == 0) g_bce[b * 2 + 1] = r[0];
    }

    // ---- level 1: row arrival; the 31st block reduces row my_b ----
    __syncthreads();
    __shared__ bool s_do_row;
    if (tid == 0) {
        __threadfence();
        s_do_row = (atomicAdd(&g_row_done[my_b], 1u) == ROW_ARRIVALS - 1);
    }
    __syncthreads();
    if (!s_do_row) return;

    {
        // sup per-class combine (tid < 100)
        float sup = 0.f, vcnt = 0.f;
        if (tid < CC) {
            float sq = 0.f, cnt = 0.f;
            const int base = my_b * (NTILE * CC) + tid;
#pragma unroll
            for (int t = 0; t < NTILE; t++) {
                sq  += g_sup_sq_p[base + t * CC];
                cnt += g_sup_cnt_p[base + t * CC];
            }
            if (cnt > 0.f) { sup = sqrtf(sq); vcnt = 1.f; }
        }

        // feat norm²: combine 5 chunk vectors per d, square (L2-hot, 80 KB)
        float na2 = 0.f, nb2 = 0.f;
#pragma unroll
        for (int which = 0; which < 2; which++) {
            const float4* base = &g_feat_vec[((which * BB + my_b) * NCHUNK) * 512];
#pragma unroll
            for (int rep = 0; rep < 2; rep++) {
                const int d4 = rep * 256 + tid;
                float4 s = make_float4(0.f, 0.f, 0.f, 0.f);
#pragma unroll
                for (int c = 0; c < NCHUNK; c++) {
                    float4 v = base[c * 512 + d4];
                    s.x += v.x; s.y += v.y; s.z += v.z; s.w += v.w;
                }
                const float d2 = s.x * s.x + s.y * s.y + s.z * s.z + s.w * s.w;
                if (which == 0) na2 += d2; else nb2 += d2;
            }
        }

#pragma unroll
        for (int o = 16; o > 0; o >>= 1) {
            sup  += __shfl_down_sync(0xffffffff, sup,  o);
            vcnt += __shfl_down_sync(0xffffffff, vcnt, o);
            na2  += __shfl_down_sync(0xffffffff, na2,  o);
            nb2  += __shfl_down_sync(0xffffffff, nb2,  o);
        }
        __shared__ float s_r[8][4];
        if (lane == 0) { s_r[wrp][0] = sup; s_r[wrp][1] = vcnt; s_r[wrp][2] = na2; s_r[wrp][3] = nb2; }
        __syncthreads();
        if (tid == 0) {
            float st = 0.f, vt = 0.f, a2 = 0.f, b2 = 0.f;
#pragma unroll
            for (int w = 0; w < 8; w++) {
                st += s_r[w][0]; vt += s_r[w][1]; a2 += s_r[w][2]; b2 += s_r[w][3];
            }
            const float na = sqrtf(a2) / (float)KK;   // ||mean feat_act||
            const float nb = sqrtf(b2) / (float)KK;   // ||mean feat_bkg||
            const float la = fmaxf(100.f - na, 0.f);
            const float t  = la + nb;
            g_row[my_b * 3 + 0] = st;
            g_row[my_b * 3 + 1] = vt;
            g_row[my_b * 3 + 2] = t * t;
        }
    }

    // ---- level 2: final arrival; the 64th row-reducer combines ----
    __syncthreads();
    __shared__ bool s_do_fin;
    if (tid == 0) {
        __threadfence();
        s_do_fin = (atomicAdd(&g_fin_done, 1u) == BB - 1);
    }
    __syncthreads();
    if (!s_do_fin) return;

    {
        float cls = 0.f, be = 0.f, st = 0.f, vt = 0.f, um = 0.f;
        if (tid < BB) {
            cls = g_bce[tid * 2 + 0];
            be  = g_bce[tid * 2 + 1];
            st  = g_row[tid * 3 + 0];
            vt  = g_row[tid * 3 + 1];
            um  = g_row[tid * 3 + 2];
        }
#pragma unroll
        for (int o = 16; o > 0; o >>= 1) {
            cls += __shfl_down_sync(0xffffffff, cls, o);
            be  += __shfl_down_sync(0xffffffff, be,  o);
            st  += __shfl_down_sync(0xffffffff, st,  o);
            vt  += __shfl_down_sync(0xffffffff, vt,  o);
            um  += __shfl_down_sync(0xffffffff, um,  o);
        }
        __shared__ float sw[2][5];
        if (lane == 0 && wrp < 2) {
            sw[wrp][0] = cls; sw[wrp][1] = be; sw[wrp][2] = st; sw[wrp][3] = vt; sw[wrp][4] = um;
        }
        __syncthreads();
        if (tid == 0) {
            const float loss = (sw[0][0] + sw[1][0]) / (float)(BB * CC)
                             + 0.0005f * ((sw[0][4] + sw[1][4]) / (float)BB)
                             + 0.2f * ((sw[0][1] + sw[1][1]) / (float)(BB * CC))
                             + 1.0f * ((sw[0][2] + sw[1][2]) / (sw[0][3] + sw[1][3]));
            out[0] = loss;
            g_fin_done = 0;                 // reset for next replay
        }
        if (tid < BB) g_row_done[tid] = 0;  // reset for next replay
    }
}

extern "C" void kernel_launch(void* const* d_in, const int* in_sizes, int n_in,
                              void* d_out, int out_size) {
    const float*  score_act = (const float*)d_in[0];
    const float*  score_bkg = (const float*)d_in[1];
    const float4* feat_act  = (const float4*)d_in[2];
    const float4* feat_bkg  = (const float4*)d_in[3];
    const float*  label     = (const float*)d_in[4];
    const float4* gt        = (const float4*)d_in[5];
    const float4* cas       = (const float4*)d_in[6];

    mega_kernel<<<TOTAL_BLOCKS, 256>>>(feat_act, feat_bkg, gt, cas,
                                       score_act, score_bkg, label,
                                       (float*)d_out);
}

// round 13
// speedup vs baseline: 1.0711x; 1.0006x over previous
#include <cuda_runtime.h>
#include <math.h>

#define BB 64
#define CC 100
#define TT 2000
#define KK 200
#define DD 2048
#define NTILE 10
#define NCHUNK 5                 // K split for feat
#define KCH (KK / NCHUNK)        // 40

#define SUP_BLOCKS   (BB * NTILE)                 // 640
#define FEAT_BLOCKS  (2 * BB * 2 * NCHUNK)        // 1280
#define BCE_BLOCKS   (BB)                         // 64
#define TOTAL_BLOCKS (SUP_BLOCKS + FEAT_BLOCKS + BCE_BLOCKS)  // 1984
#define ROW_ARRIVALS (NTILE + 2 * 2 * NCHUNK + 1) // 31 per row

// Deterministic partial buffers — plain writes, no zeroing needed.
__device__ float  g_sup_sq_p[BB * NTILE * CC];        // [b][tile][c]
__device__ float  g_sup_cnt_p[BB * NTILE * CC];       // [b][tile][c]
__device__ float4 g_feat_vec[2 * BB * NCHUNK * 512];  // [which][b][chunk][d4]
__device__ float  g_bce[BB * 2];                      // [b][{cls,be}]
__device__ float  g_row[BB * 3];                      // [b][{sup, vcnt, um}]
// Arrival counters — reset by the final block each run (graph-replay safe).
__device__ unsigned int g_row_done[BB];
__device__ unsigned int g_fin_done;

__global__ void __launch_bounds__(256) mega_kernel(
        const float4* __restrict__ fa, const float4* __restrict__ fb,
        const float4* __restrict__ gt, const float4* __restrict__ cas,
        const float* __restrict__ score_act,
        const float* __restrict__ score_bkg,
        const float* __restrict__ label,
        float* __restrict__ out) {
    const int blk = blockIdx.x;
    const int tid = threadIdx.x;       // 0..255
    const int tx  = tid & 31;
    const int ty  = tid >> 5;          // 0..7
    const int lane = tx, wrp = ty;

    int my_b;  // the batch row this block contributes to

    if (blk < SUP_BLOCKS) {
        // ---- sup tile: (b, tile) over 200 time steps ----
        const int b    = blk / NTILE;
        const int tile = blk % NTILE;
        const int tb   = tile * 200;
        my_b = b;

        float4 sq  = make_float4(0.f, 0.f, 0.f, 0.f);
        float4 cnt = make_float4(0.f, 0.f, 0.f, 0.f);

        if (tx < CC / 4) {
            const size_t base = (size_t)b * TT * (CC / 4) + (size_t)tb * (CC / 4) + tx;
#pragma unroll 5
            for (int j = 0; j < 25; j++) {
                const size_t idx = base + (size_t)(ty + 8 * j) * (CC / 4);
                float4 g = gt[idx];
                float4 c = cas[idx];
                float pm, d;
                pm = (g.x > 0.5f) ? 1.f : 0.f; d = c.x - pm; sq.x += d * d; cnt.x += pm;
                pm = (g.y > 0.5f) ? 1.f : 0.f; d = c.y - pm; sq.y += d * d; cnt.y += pm;
                pm = (g.z > 0.5f) ? 1.f : 0.f; d = c.z - pm; sq.z += d * d; cnt.z += pm;
                pm = (g.w > 0.5f) ? 1.f : 0.f; d = c.w - pm; sq.w += d * d; cnt.w += pm;
            }
        }

        __shared__ float s_sq[CC], s_cnt[CC];
        if (tid < CC) { s_sq[tid] = 0.f; s_cnt[tid] = 0.f; }
        __syncthreads();
        if (tx < CC / 4) {
            atomicAdd(&s_sq[tx * 4 + 0], sq.x);  atomicAdd(&s_cnt[tx * 4 + 0], cnt.x);
            atomicAdd(&s_sq[tx * 4 + 1], sq.y);  atomicAdd(&s_cnt[tx * 4 + 1], cnt.y);
            atomicAdd(&s_sq[tx * 4 + 2], sq.z);  atomicAdd(&s_cnt[tx * 4 + 2], cnt.z);
            atomicAdd(&s_sq[tx * 4 + 3], sq.w);  atomicAdd(&s_cnt[tx * 4 + 3], cnt.w);
        }
        __syncthreads();
        if (tid < CC) {
            const int o = b * (NTILE * CC) + tile * CC + tid;
            g_sup_sq_p[o]  = s_sq[tid];
            g_sup_cnt_p[o] = s_cnt[tid];
        }
    } else if (blk < SUP_BLOCKS + FEAT_BLOCKS) {
        // ---- feat chunk: (which, b, dpart, chunk) — 40 k-steps, vector partial ----
        const int idx   = blk - SUP_BLOCKS;         // 0..1279
        const int which = idx / (BB * 2 * NCHUNK);  // 0..1
        int rem = idx % (BB * 2 * NCHUNK);
        const int b     = rem / (2 * NCHUNK);       // 0..63
        rem %= (2 * NCHUNK);
        const int dpart = rem / NCHUNK;             // 0..1
        const int chunk = rem % NCHUNK;             // 0..4
        my_b = b;
        const float4* __restrict__ f = which ? fb : fa;

        const int d4 = dpart * 256 + tid;           // 0..511
        const float4* p = f + (size_t)b * KK * (DD / 4)
                            + (size_t)(chunk * KCH) * (DD / 4) + d4;

        float4 s = make_float4(0.f, 0.f, 0.f, 0.f);
#pragma unroll 8
        for (int k = 0; k < KCH; k++) {
            float4 v = p[(size_t)k * (DD / 4)];
            s.x += v.x; s.y += v.y; s.z += v.z; s.w += v.w;
        }
        g_feat_vec[((which * BB + b) * NCHUNK + chunk) * 512 + d4] = s;
    } else {
        // ---- BCE partials for row b (all 256 threads hit barriers) ----
        const int b = blk - SUP_BLOCKS - FEAT_BLOCKS;
        my_b = b;
        __shared__ float r[128];
        __shared__ float s_rowsum;
        const int i = b * CC + ((tid < CC) ? tid : 0);
        const float lab = (tid < CC) ? label[i] : 0.f;

        if (tid < 128) r[tid] = lab;
        __syncthreads();
#pragma unroll
        for (int o = 64; o > 0; o >>= 1) {
            if (tid < o) r[tid] += r[tid + o];
            __syncthreads();
        }
        if (tid == 0) s_rowsum = r[0];
        __syncthreads();
        const float rowsum = s_rowsum;

        float cls = 0.f, be = 0.f;
        const float invC = 1.0f / (float)CC;
        if (tid < CC) {
            const float y = lab / rowsum;
            const float p = score_act[i];
            cls = -(y * fmaxf(logf(p), -100.f) + (1.f - y) * fmaxf(logf(1.f - p), -100.f));
            const float pb = score_bkg[i];
            be = -(invC * fmaxf(logf(pb), -100.f) + (1.f - invC) * fmaxf(logf(1.f - pb), -100.f));
        }
        if (tid < 128) r[tid] = cls;
        __syncthreads();
#pragma unroll
        for (int o = 64; o > 0; o >>= 1) {
            if (tid < o) r[tid] += r[tid + o];
            __syncthreads();
        }
        if (tid == 0) g_bce[b * 2 + 0] = r[0];
        __syncthreads();
        if (tid < 128) r[tid] = be;
        __syncthreads();
#pragma unroll
        for (int o = 64; o > 0; o >>= 1) {
            if (tid < o) r[tid] += r[tid + o];
            __syncthreads();
        }
        if (tid == 0) g_bce[b * 2 + 1] = r[0];
    }

    // ---- level 1: row arrival; the 31st block reduces row my_b ----
    __syncthreads();
    __shared__ bool s_do_row;
    if (tid == 0) {
        __threadfence();
        s_do_row = (atomicAdd(&g_row_done[my_b], 1u) == ROW_ARRIVALS - 1);
    }
    __syncthreads();
    if (!s_do_row) return;

    {
        // sup per-class combine (tid < 100)
        float sup = 0.f, vcnt = 0.f;
        if (tid < CC) {
            float sq = 0.f, cnt = 0.f;
            const int base = my_b * (NTILE * CC) + tid;
#pragma unroll
            for (int t = 0; t < NTILE; t++) {
                sq  += g_sup_sq_p[base + t * CC];
                cnt += g_sup_cnt_p[base + t * CC];
            }
            if (cnt > 0.f) { sup = sqrtf(sq); vcnt = 1.f; }
        }

        // feat norm²: combine 5 chunk vectors per d, square (L2-hot, 80 KB)
        float na2 = 0.f, nb2 = 0.f;
#pragma unroll
        for (int which = 0; which < 2; which++) {
            const float4* base = &g_feat_vec[((which * BB + my_b) * NCHUNK) * 512];
#pragma unroll
            for (int rep = 0; rep < 2; rep++) {
                const int d4 = rep * 256 + tid;
                float4 s = make_float4(0.f, 0.f, 0.f, 0.f);
#pragma unroll
                for (int c = 0; c < NCHUNK; c++) {
                    float4 v = base[c * 512 + d4];
                    s.x += v.x; s.y += v.y; s.z += v.z; s.w += v.w;
                }
                const float d2 = s.x * s.x + s.y * s.y + s.z * s.z + s.w * s.w;
                if (which == 0) na2 += d2; else nb2 += d2;
            }
        }

#pragma unroll
        for (int o = 16; o > 0; o >>= 1) {
            sup  += __shfl_down_sync(0xffffffff, sup,  o);
            vcnt += __shfl_down_sync(0xffffffff, vcnt, o);
            na2  += __shfl_down_sync(0xffffffff, na2,  o);
            nb2  += __shfl_down_sync(0xffffffff, nb2,  o);
        }
        __shared__ float s_r[8][4];
        if (lane == 0) { s_r[wrp][0] = sup; s_r[wrp][1] = vcnt; s_r[wrp][2] = na2; s_r[wrp][3] = nb2; }
        __syncthreads();
        if (tid == 0) {
            float st = 0.f, vt = 0.f, a2 = 0.f, b2 = 0.f;
#pragma unroll
            for (int w = 0; w < 8; w++) {
                st += s_r[w][0]; vt += s_r[w][1]; a2 += s_r[w][2]; b2 += s_r[w][3];
            }
            const float na = sqrtf(a2) / (float)KK;   // ||mean feat_act||
            const float nb = sqrtf(b2) / (float)KK;   // ||mean feat_bkg||
            const float la = fmaxf(100.f - na, 0.f);
            const float t  = la + nb;
            g_row[my_b * 3 + 0] = st;
            g_row[my_b * 3 + 1] = vt;
            g_row[my_b * 3 + 2] = t * t;
        }
    }

    // ---- level 2: final arrival; the 64th row-reducer combines ----
    __syncthreads();
    __shared__ bool s_do_fin;
    if (tid == 0) {
        __threadfence();
        s_do_fin = (atomicAdd(&g_fin_done, 1u) == BB - 1);
    }
    __syncthreads();
    if (!s_do_fin) return;

    {
        float cls = 0.f, be = 0.f, st = 0.f, vt = 0.f, um = 0.f;
        if (tid < BB) {
            cls = g_bce[tid * 2 + 0];
            be  = g_bce[tid * 2 + 1];
            st  = g_row[tid * 3 + 0];
            vt  = g_row[tid * 3 + 1];
            um  = g_row[tid * 3 + 2];
        }
#pragma unroll
        for (int o = 16; o > 0; o >>= 1) {
            cls += __shfl_down_sync(0xffffffff, cls, o);
            be  += __shfl_down_sync(0xffffffff, be,  o);
            st  += __shfl_down_sync(0xffffffff, st,  o);
            vt  += __shfl_down_sync(0xffffffff, vt,  o);
            um  += __shfl_down_sync(0xffffffff, um,  o);
        }
        __shared__ float sw[2][5];
        if (lane == 0 && wrp < 2) {
            sw[wrp][0] = cls; sw[wrp][1] = be; sw[wrp][2] = st; sw[wrp][3] = vt; sw[wrp][4] = um;
        }
        __syncthreads();
        if (tid == 0) {
            const float loss = (sw[0][0] + sw[1][0]) / (float)(BB * CC)
                             + 0.0005f * ((sw[0][4] + sw[1][4]) / (float)BB)
                             + 0.2f * ((sw[0][1] + sw[1][1]) / (float)(BB * CC))
                             + 1.0f * ((sw[0][2] + sw[1][2]) / (sw[0][3] + sw[1][3]));
            out[0] = loss;
            g_fin_done = 0;                 // reset for next replay
        }
        if (tid < BB) g_row_done[tid] = 0;  // reset for next replay
    }
}

extern "C" void kernel_launch(void* const* d_in, const int* in_sizes, int n_in,
                              void* d_out, int out_size) {
    const float*  score_act = (const float*)d_in[0];
    const float*  score_bkg = (const float*)d_in[1];
    const float4* feat_act  = (const float4*)d_in[2];
    const float4* feat_bkg  = (const float4*)d_in[3];
    const float*  label     = (const float*)d_in[4];
    const float4* gt        = (const float4*)d_in[5];
    const float4* cas       = (const float4*)d_in[6];

    mega_kernel<<<TOTAL_BLOCKS, 256>>>(feat_act, feat_bkg, gt, cas,
                                       score_act, score_bkg, label,
                                       (float*)d_out);
}